// round 4
// baseline (speedup 1.0000x reference)
#include <cuda_runtime.h>
#include <math_constants.h>

// KNN max-pooling: out[q, :] = max over j in 0..15 of feat[idx[q, j], :]
// feat: [100000, 64] f32, idx: [100000, 16] int32 (JAX downgrades int64->int32
// without x64 mode), out: [100000, 64] f32.
//
// Layout: 16 threads per query (2 queries per warp). Lane l (0..15) owns
// channels [4l, 4l+4) as a float4. Each lane loads idx[q, l]; neighbor j's
// pre-scaled row offset is broadcast via a 32-bit shfl within the 16-lane
// segment. Gathered loads are LDG.128 and the 16 lanes cover the full 256 B
// feature row contiguously -> fully coalesced, L2-bandwidth-bound (~450 MB of
// L2 traffic; feat fits in L2).

#define NSAMPLE 16
#define C4 16  // 64 channels / 4 per float4

__global__ void __launch_bounds__(256) knn_pool_kernel(
    const float4* __restrict__ feat,   // [N, 16] float4
    const int* __restrict__ idx,       // [M, 16] int32
    float4* __restrict__ out,          // [M, 16] float4
    int M)
{
    int tid = blockIdx.x * blockDim.x + threadIdx.x;
    int q = tid >> 4;
    int lane = tid & 15;
    if (q >= M) return;

    // Coalesced idx load: 16 lanes read 16 consecutive int32 (64 B).
    // Pre-scale to a float4 row offset (fits in 32 bits: 100000*16 < 2^31).
    int my_off = idx[q * NSAMPLE + lane] * C4;

    float4 m;
    m.x = -CUDART_INF_F; m.y = -CUDART_INF_F;
    m.z = -CUDART_INF_F; m.w = -CUDART_INF_F;

    #pragma unroll
    for (int j = 0; j < NSAMPLE; ++j) {
        // Broadcast neighbor j's pre-scaled row offset within the 16-lane segment
        int nb = __shfl_sync(0xFFFFFFFFu, my_off, j, 16);
        float4 v = __ldg(&feat[nb + lane]);
        m.x = fmaxf(m.x, v.x);
        m.y = fmaxf(m.y, v.y);
        m.z = fmaxf(m.z, v.z);
        m.w = fmaxf(m.w, v.w);
    }

    out[q * C4 + lane] = m;
}

extern "C" void kernel_launch(void* const* d_in, const int* in_sizes, int n_in,
                              void* d_out, int out_size)
{
    const float4* feat = (const float4*)d_in[0];
    const int* idx     = (const int*)d_in[1];
    float4* out        = (float4*)d_out;

    int M = in_sizes[1] / NSAMPLE;  // idx has M*16 elements

    int total_threads = M * 16;
    int block = 256;
    int grid = (total_threads + block - 1) / block;
    knn_pool_kernel<<<grid, block>>>(feat, idx, out, M);
}